// round 4
// baseline (speedup 1.0000x reference)
#include <cuda_runtime.h>
#include <math_constants.h>

#define PRE    1024
#define POSTN  1024
#define BATCH  32
#define NBK    64          // coarse time buckets over [0,2)
#define WIDTH  0.03125f
#define CAP    96          // per-flagged-bucket capacity (avg ~16, peak-density avg 32)
#define MAXF   8           // flagged buckets processed in parallel (one per warp)
#define NTH    256
#define FULLM  0xffffffffu
#define SPLITB 24          // pass 0 = buckets [0,24)  <=>  t < 0.75

// Transposed copies of delays/weights: [post][pre], coalesced for the main kernel.
__device__ float g_dT[POSTN * PRE];
__device__ float g_wT[POSTN * PRE];

// ---------------------------------------------------------------------------
__global__ void transpose_kernel(const float* __restrict__ W,
                                 const float* __restrict__ D)
{
    __shared__ float tw[32][33];
    __shared__ float td[32][33];
    int x  = blockIdx.x * 32 + threadIdx.x;
    int y0 = blockIdx.y * 32;
#pragma unroll
    for (int j = 0; j < 32; j += 8) {
        tw[threadIdx.y + j][threadIdx.x] = W[(size_t)(y0 + threadIdx.y + j) * POSTN + x];
        td[threadIdx.y + j][threadIdx.x] = D[(size_t)(y0 + threadIdx.y + j) * POSTN + x];
    }
    __syncthreads();
    int xo  = blockIdx.y * 32 + threadIdx.x;
    int yo0 = blockIdx.x * 32;
#pragma unroll
    for (int j = 0; j < 32; j += 8) {
        g_wT[(size_t)(yo0 + threadIdx.y + j) * PRE + xo] = tw[threadIdx.x][threadIdx.y + j];
        g_dT[(size_t)(yo0 + threadIdx.y + j) * PRE + xo] = td[threadIdx.x][threadIdx.y + j];
    }
}

// ---------------------------------------------------------------------------
// One block per (batch, post). Level-crossing search on V(t)=cumw*t-cumwt.
// Pass 0 bins only events with t<0.75 (28% of events) and searches buckets
// 0..23 (crossing is there with prob ~1-3e-6). Pass 1 adds the rest.
// Flagged buckets are processed in PARALLEL, one warp each.
// ---------------------------------------------------------------------------
__global__ __launch_bounds__(NTH, 6)
void equaltime_kernel(const float* __restrict__ spikes,
                      const float* __restrict__ thresholds,
                      float* __restrict__ out)
{
    __shared__ float sW[NBK], sWT[NBK], sWp[NBK];
    __shared__ float scW[NBK], scWT[NBK];
    __shared__ int   sflag[NBK];
    __shared__ int   snflag;
    __shared__ float sTot[2];
    __shared__ int   scnt[MAXF];
    __shared__ float sres[MAXF];
    __shared__ float bufT[MAXF][CAP], bufW[MAXF][CAP];
    __shared__ int   sdone;
    __shared__ float sfinal;

    const int tid  = threadIdx.x;
    const int bid  = blockIdx.x;
    const int post = bid >> 5;
    const int b    = bid & 31;
    const int lane = tid & 31;
    const int wid  = tid >> 5;

    const float theta = thresholds[post];
    const float* dT = g_dT + (size_t)post * PRE;
    const float* wT = g_wT + (size_t)post * PRE;
    const float* sp = spikes + (size_t)b * PRE;

    if (tid < NBK) { sW[tid] = 0.f; sWT[tid] = 0.f; sWp[tid] = 0.f; }
    if (tid == 0)  sdone = 0;
    __syncthreads();

    // events in registers
    const int i0 = tid * 4;
    float4 s4 = *reinterpret_cast<const float4*>(sp + i0);
    float4 d4 = *reinterpret_cast<const float4*>(dT + i0);
    float4 w4 = *reinterpret_cast<const float4*>(wT + i0);
    float tv[4] = { s4.x + d4.x, s4.y + d4.y, s4.z + d4.z, s4.w + d4.w };
    float wv[4] = { w4.x, w4.y, w4.z, w4.w };
    int   bk[4];
#pragma unroll
    for (int q = 0; q < 4; q++) {
        int bb = (int)(tv[q] * 32.0f);
        bk[q] = max(0, min(bb, NBK - 1));
    }

    for (int pass = 0; pass < 2; pass++) {
        const int blo = pass ? SPLITB : 0;
        const int bhi = pass ? NBK : SPLITB;

        // ---- bin this pass's events (3 shared atomics each) ----
#pragma unroll
        for (int q = 0; q < 4; q++) {
            if (bk[q] >= blo && bk[q] < bhi) {
                atomicAdd(&sW[bk[q]],  wv[q]);
                atomicAdd(&sWT[bk[q]], wv[q] * tv[q]);
                atomicAdd(&sWp[bk[q]], fmaxf(wv[q], 0.f));
            }
        }
        __syncthreads();

        // ---- warp 0: boundary scan over 64 buckets + flagging ----
        if (wid == 0) {
            float w0  = sW[lane],  w1  = sW[lane + 32];
            float wt0 = sWT[lane], wt1 = sWT[lane + 32];
            float a0 = w0, a1 = w1, b0 = wt0, b1 = wt1;
#pragma unroll
            for (int o = 1; o < 32; o <<= 1) {
                float u0 = __shfl_up_sync(FULLM, a0, o);
                float u1 = __shfl_up_sync(FULLM, a1, o);
                float v0 = __shfl_up_sync(FULLM, b0, o);
                float v1 = __shfl_up_sync(FULLM, b1, o);
                if (lane >= o) { a0 += u0; a1 += u1; b0 += v0; b1 += v1; }
            }
            float T0  = __shfl_sync(FULLM, a0, 31);
            float TW0 = __shfl_sync(FULLM, b0, 31);
            a1 += T0; b1 += TW0;
            float e0 = a0 - w0,  e1 = a1 - w1;
            float f0 = b0 - wt0, f1 = b1 - wt1;
            scW[lane] = e0;  scW[lane + 32] = e1;
            scWT[lane] = f0; scWT[lane + 32] = f1;
            if (lane == 31) { sTot[0] = a1; sTot[1] = b1; }
            float B0 = lane * WIDTH, B1 = (lane + 32) * WIDTH;
            float V0 = e0 * B0 - f0;
            float V1 = e1 * B1 - f1;
            bool fl0 = (lane >= blo) && (lane < bhi) &&
                       (V0 + fmaxf(e0 + sWp[lane], 0.f) * WIDTH >= theta);
            bool fl1 = ((lane + 32) >= blo) && ((lane + 32) < bhi) &&
                       (V1 + fmaxf(e1 + sWp[lane + 32], 0.f) * WIDTH >= theta);
            unsigned m0 = __ballot_sync(FULLM, fl0);
            unsigned m1 = __ballot_sync(FULLM, fl1);
            int n0 = __popc(m0);
            if (fl0) sflag[__popc(m0 & ((1u << lane) - 1))] = lane;
            if (fl1) sflag[n0 + __popc(m1 & ((1u << lane) - 1))] = lane + 32;
            if (lane == 0) snflag = n0 + __popc(m1);
        }
        __syncthreads();

        const int nf = snflag;
        for (int g = 0; g < nf; g += MAXF) {
            const int ng = min(nf - g, MAXF);
            if (tid < MAXF) { scnt[tid] = 0; sres[tid] = CUDART_INF_F; }
            __syncthreads();

            // ---- compact events of the ng flagged buckets (all threads) ----
#pragma unroll
            for (int q = 0; q < 4; q++) {
                int bq = bk[q];
                for (int f = 0; f < ng; f++) {
                    if (sflag[g + f] == bq) {
                        int p = atomicAdd(&scnt[f], 1);
                        if (p < CAP) { bufT[f][p] = tv[q]; bufW[f][p] = wv[q]; }
                        break;
                    }
                }
            }
            __syncthreads();

            // ---- warp f: sort + evaluate flagged bucket f ----
            if (wid < ng) {
                const int f = wid;
                const int j = sflag[g + f];
                const int n = min(scnt[f], CAP);
                float cw = scW[j], cwt = scWT[j];
                bool  found = false;
                float tmp = 0.f;

                if (n > 0) {
                    // rank sort (position tie-break; tie order irrelevant for V)
                    float rt[3], rw[3];
                    int   rk[3];
#pragma unroll
                    for (int r = 0; r < 3; r++) {
                        int p = lane + 32 * r;
                        bool on = (p < n);
                        rt[r] = on ? bufT[f][p] : CUDART_INF_F;
                        rw[r] = on ? bufW[f][p] : 0.f;
                        rk[r] = 0;
                    }
                    __syncwarp();
#pragma unroll
                    for (int r2 = 0; r2 < 3; r2++) {
                        if (r2 * 32 < n) {
                            int m = min(n - r2 * 32, 32);
                            for (int s = 0; s < m; s++) {
                                float tb = __shfl_sync(FULLM, rt[r2], s);
                                int   pb = r2 * 32 + s;
#pragma unroll
                                for (int q2 = 0; q2 < 3; q2++) {
                                    int myp = lane + 32 * q2;
                                    if (myp < n)
                                        rk[q2] += (tb < rt[q2]) ||
                                                  (tb == rt[q2] && pb < myp);
                                }
                            }
                        }
                    }
#pragma unroll
                    for (int q2 = 0; q2 < 3; q2++)
                        if (lane + 32 * q2 < n) {
                            bufT[f][rk[q2]] = rt[q2];
                            bufW[f][rk[q2]] = rw[q2];
                        }
                    __syncwarp();

                    // in-order eval, 32 events per chunk
                    for (int c = 0; c < n && !found; c += 32) {
                        int  k  = c + lane;
                        bool on = (k < n);
                        float tk = on ? bufT[f][k] : 0.f;
                        float wk = on ? bufW[f][k] : 0.f;
                        float swi = wk, swti = wk * tk;
#pragma unroll
                        for (int o = 1; o < 32; o <<= 1) {
                            float u = __shfl_up_sync(FULLM, swi,  o);
                            float v = __shfl_up_sync(FULLM, swti, o);
                            if (lane >= o) { swi += u; swti += v; }
                        }
                        float CWp  = cw  + swi  - wk;
                        float CWTp = cwt + swti - wk * tk;
                        float V    = CWp * tk - CWTp;
                        bool cross = on && (V >= theta) && (CWp > 0.f);
                        unsigned cb = __ballot_sync(FULLM, cross);
                        if (cb) {
                            int fl = __ffs(cb) - 1;
                            float cand = (theta + CWTp) / CWp;
                            tmp = __shfl_sync(FULLM, cand, fl);
                            found = true;
                        } else {
                            int lastl = min(31, n - 1 - c);
                            cw  += __shfl_sync(FULLM, swi,  lastl);
                            cwt += __shfl_sync(FULLM, swti, lastl);
                        }
                    }
                }
                if (!found && cw > 0.f) {
                    float Bend = (float)(j + 1) * WIDTH;
                    if (cw * Bend - cwt >= theta) {   // crossing after last event
                        tmp = (theta + cwt) / cw;
                        found = true;
                    }
                }
                if (found && lane == 0) sres[f] = tmp;
            }
            __syncthreads();

            if (tid == 0) {
                for (int f = 0; f < ng; f++)
                    if (sres[f] < CUDART_INF_F) { sfinal = sres[f]; sdone = 1; break; }
            }
            __syncthreads();
            if (sdone) break;
        }
        if (sdone) break;
    }

    if (tid == 0) {
        float r;
        if (sdone) r = sfinal;
        else {
            float cw = sTot[0], cwt = sTot[1];
            r = (cw > 0.f) ? (theta + cwt) / cw : CUDART_INF_F;
        }
        out[(size_t)b * POSTN + post] = r;
    }
}

// ---------------------------------------------------------------------------
extern "C" void kernel_launch(void* const* d_in, const int* in_sizes, int n_in,
                              void* d_out, int out_size)
{
    const float* spikes  = (const float*)d_in[0];  // [32, 1024]
    const float* weights = (const float*)d_in[1];  // [1024, 1024]
    const float* delays  = (const float*)d_in[2];  // [1024, 1024]
    const float* thr     = (const float*)d_in[3];  // [1024]
    float* out = (float*)d_out;                    // [32, 1024]

    dim3 tb(32, 8);
    dim3 tg(POSTN / 32, PRE / 32);
    transpose_kernel<<<tg, tb>>>(weights, delays);

    equaltime_kernel<<<BATCH * POSTN, NTH>>>(spikes, thr, out);
}

// round 6
// speedup vs baseline: 2.7578x; 2.7578x over previous
#include <cuda_runtime.h>
#include <math_constants.h>

#define PRE    1024
#define POSTN  1024
#define BATCH  32
#define NBK    64
#define WIDTH  0.03125f
#define CAP    96
#define NTH    256
#define NWARP  8
#define FULLM  0xffffffffu
#define P0B    24          // pass-0 buckets [0,24) <=> t < 0.75

// Transposed copies of delays/weights: [post][pre]
__device__ float g_dT[POSTN * PRE];
__device__ float g_wT[POSTN * PRE];

// ---------------------------------------------------------------------------
__global__ void transpose_kernel(const float* __restrict__ W,
                                 const float* __restrict__ D)
{
    __shared__ float tw[32][33];
    __shared__ float td[32][33];
    int x  = blockIdx.x * 32 + threadIdx.x;
    int y0 = blockIdx.y * 32;
#pragma unroll
    for (int j = 0; j < 32; j += 8) {
        tw[threadIdx.y + j][threadIdx.x] = W[(size_t)(y0 + threadIdx.y + j) * POSTN + x];
        td[threadIdx.y + j][threadIdx.x] = D[(size_t)(y0 + threadIdx.y + j) * POSTN + x];
    }
    __syncthreads();
    int xo  = blockIdx.y * 32 + threadIdx.x;
    int yo0 = blockIdx.x * 32;
#pragma unroll
    for (int j = 0; j < 32; j += 8) {
        g_wT[(size_t)(yo0 + threadIdx.y + j) * PRE + xo] = tw[threadIdx.x][threadIdx.y + j];
        g_dT[(size_t)(yo0 + threadIdx.y + j) * PRE + xo] = td[threadIdx.x][threadIdx.y + j];
    }
}

// ---------------------------------------------------------------------------
// Gather events of bucket j from global (L1-hot), sort, evaluate level
// crossing of V(t)=cumw*t-cumwt against theta. Warp-collective. Returns
// true + *outres if the first crossing lies in (or drifts through) bucket j.
// ---------------------------------------------------------------------------
__device__ __forceinline__ bool gse(
    int j, float theta, float cw, float cwt,
    const float* __restrict__ sp, const float* __restrict__ dT,
    const float* __restrict__ wT,
    float* bT, float* bW, int lane, float* outres)
{
    // gather bucket-j events
    int cnt = 0;
#pragma unroll
    for (int r = 0; r < 8; r++) {
        int i0 = r * 128 + lane * 4;
        float4 s4 = *reinterpret_cast<const float4*>(sp + i0);
        float4 d4 = *reinterpret_cast<const float4*>(dT + i0);
        float4 w4 = *reinterpret_cast<const float4*>(wT + i0);
        float tq[4] = { s4.x + d4.x, s4.y + d4.y, s4.z + d4.z, s4.w + d4.w };
        float wq[4] = { w4.x, w4.y, w4.z, w4.w };
#pragma unroll
        for (int q = 0; q < 4; q++) {
            int bb = (int)(tq[q] * 32.0f);
            bb = max(0, min(bb, NBK - 1));
            bool in = (bb == j);
            unsigned m = __ballot_sync(FULLM, in);
            int pos = cnt + __popc(m & ((1u << lane) - 1));
            if (in && pos < CAP) { bT[pos] = tq[q]; bW[pos] = wq[q]; }
            cnt += __popc(m);
        }
    }
    cnt = min(cnt, CAP);
    __syncwarp();

    if (cnt > 0) {
        // rank sort (position tie-break; tie order irrelevant for V)
        float rt[3], rw[3];
        int   rk[3];
#pragma unroll
        for (int r = 0; r < 3; r++) {
            int p = lane + 32 * r;
            bool on = (p < cnt);
            rt[r] = on ? bT[p] : CUDART_INF_F;
            rw[r] = on ? bW[p] : 0.f;
            rk[r] = 0;
        }
        __syncwarp();
        for (int s = 0; s < cnt; s++) {
            float tb = bT[s];
#pragma unroll
            for (int q = 0; q < 3; q++) {
                int myp = lane + 32 * q;
                if (myp < cnt)
                    rk[q] += (tb < rt[q]) || (tb == rt[q] && s < myp);
            }
        }
        __syncwarp();
#pragma unroll
        for (int q = 0; q < 3; q++)
            if (lane + 32 * q < cnt) { bT[rk[q]] = rt[q]; bW[rk[q]] = rw[q]; }
        __syncwarp();
    }

    // in-order eval: first event with V(t_k) >= theta
    bool  found = false;
    float tmp = 0.f;
    for (int c0 = 0; c0 < cnt && !found; c0 += 32) {
        int  k  = c0 + lane;
        bool on = (k < cnt);
        float tk = on ? bT[k] : 0.f;
        float wk = on ? bW[k] : 0.f;
        float swi = wk, swti = wk * tk;
#pragma unroll
        for (int o = 1; o < 32; o <<= 1) {
            float u = __shfl_up_sync(FULLM, swi,  o);
            float v = __shfl_up_sync(FULLM, swti, o);
            if (lane >= o) { swi += u; swti += v; }
        }
        float CWp  = cw  + swi  - wk;         // prefix BEFORE event k
        float CWTp = cwt + swti - wk * tk;
        float V    = CWp * tk - CWTp;
        bool cross = on && (V >= theta) && (CWp > 0.f);
        unsigned cb = __ballot_sync(FULLM, cross);
        if (cb) {
            int fl = __ffs(cb) - 1;
            float cand = (theta + CWTp) / CWp;
            tmp = __shfl_sync(FULLM, cand, fl);
            found = true;
        } else {
            int lastl = min(31, cnt - 1 - c0);
            cw  += __shfl_sync(FULLM, swi,  lastl);
            cwt += __shfl_sync(FULLM, swti, lastl);
        }
    }
    if (!found) {
        // drift crossing after last bucket event, before bucket edge
        float edge = (float)(j + 1) * WIDTH;
        if (cw > 0.f && cw * edge - cwt >= theta) {
            tmp = (theta + cwt) / cw;
            found = true;
        }
    }
    if (found) *outres = tmp;
    return found;
}

// ---------------------------------------------------------------------------
// One WARP per (batch, post) problem. No block-wide barriers.
// ---------------------------------------------------------------------------
__global__ __launch_bounds__(NTH)
void equaltime_kernel(const float* __restrict__ spikes,
                      const float* __restrict__ thresholds,
                      float* __restrict__ out)
{
    __shared__ float sW[NWARP][NBK], sWT[NWARP][NBK], sWp[NWARP][NBK];
    __shared__ float bufT[NWARP][CAP], bufW[NWARP][CAP];

    const int lane = threadIdx.x & 31;
    const int wid  = threadIdx.x >> 5;
    const int pid  = blockIdx.x * NWARP + wid;
    const int post = pid >> 5;
    const int b    = pid & 31;

    const float theta = thresholds[post];
    const float* dT = g_dT + (size_t)post * PRE;
    const float* wT = g_wT + (size_t)post * PRE;
    const float* sp = spikes + (size_t)b * PRE;
    float* mW  = sW[wid];
    float* mWT = sWT[wid];
    float* mWp = sWp[wid];

    // zero pass-0 bins
    if (lane < P0B) { mW[lane] = 0.f; mWT[lane] = 0.f; mWp[lane] = 0.f; }
    __syncwarp();

    // ---- pass-0 binning: only events in buckets [0,24) ----
#pragma unroll
    for (int r = 0; r < 8; r++) {
        int i0 = r * 128 + lane * 4;
        float4 s4 = *reinterpret_cast<const float4*>(sp + i0);
        float4 d4 = *reinterpret_cast<const float4*>(dT + i0);
        float4 w4 = *reinterpret_cast<const float4*>(wT + i0);
        float tq[4] = { s4.x + d4.x, s4.y + d4.y, s4.z + d4.z, s4.w + d4.w };
        float wq[4] = { w4.x, w4.y, w4.z, w4.w };
#pragma unroll
        for (int q = 0; q < 4; q++) {
            int bb = (int)(tq[q] * 32.0f);
            bb = max(0, min(bb, NBK - 1));
            if (bb < P0B) {
                atomicAdd(&mW[bb],  wq[q]);
                atomicAdd(&mWT[bb], wq[q] * tq[q]);
                atomicAdd(&mWp[bb], fmaxf(wq[q], 0.f));
            }
        }
    }
    __syncwarp();

    // ---- scan pass-0 bins, flag candidate buckets ----
    float wj  = (lane < P0B) ? mW[lane]  : 0.f;
    float wtj = (lane < P0B) ? mWT[lane] : 0.f;
    float a = wj, c = wtj;
#pragma unroll
    for (int o = 1; o < 32; o <<= 1) {
        float u = __shfl_up_sync(FULLM, a, o);
        float v = __shfl_up_sync(FULLM, c, o);
        if (lane >= o) { a += u; c += v; }
    }
    float e = a - wj, f = c - wtj;                 // exclusive prefixes
    float V = e * (lane * WIDTH) - f;
    float wp = (lane < P0B) ? mWp[lane] : 0.f;
    bool fl = (lane < P0B) && (V + fmaxf(e + wp, 0.f) * WIDTH >= theta);
    unsigned fm = __ballot_sync(FULLM, fl);

    float res = CUDART_INF_F;
    bool  done = false;
    while (fm) {
        int j = __ffs(fm) - 1;
        fm &= fm - 1;
        float cw0  = __shfl_sync(FULLM, e, j);
        float cwt0 = __shfl_sync(FULLM, f, j);
        if (gse(j, theta, cw0, cwt0, sp, dT, wT,
                bufT[wid], bufW[wid], lane, &res)) { done = true; break; }
    }

    // ---- pass 1 (crossing at t >= 0.75; probability ~1e-14, exact path) ----
    if (!done) {
        for (int jj = P0B + lane; jj < NBK; jj += 32) {
            mW[jj] = 0.f; mWT[jj] = 0.f; mWp[jj] = 0.f;
        }
        __syncwarp();
#pragma unroll
        for (int r = 0; r < 8; r++) {
            int i0 = r * 128 + lane * 4;
            float4 s4 = *reinterpret_cast<const float4*>(sp + i0);
            float4 d4 = *reinterpret_cast<const float4*>(dT + i0);
            float4 w4 = *reinterpret_cast<const float4*>(wT + i0);
            float tq[4] = { s4.x + d4.x, s4.y + d4.y, s4.z + d4.z, s4.w + d4.w };
            float wq[4] = { w4.x, w4.y, w4.z, w4.w };
#pragma unroll
            for (int q = 0; q < 4; q++) {
                int bb = (int)(tq[q] * 32.0f);
                bb = max(0, min(bb, NBK - 1));
                if (bb >= P0B) {
                    atomicAdd(&mW[bb],  wq[q]);
                    atomicAdd(&mWT[bb], wq[q] * tq[q]);
                    atomicAdd(&mWp[bb], fmaxf(wq[q], 0.f));
                }
            }
        }
        __syncwarp();

        // scan all 64 buckets (lane handles lane and lane+32)
        float w0  = mW[lane],  w1  = mW[lane + 32];
        float wt0 = mWT[lane], wt1 = mWT[lane + 32];
        float a0 = w0, a1 = w1, b0 = wt0, b1 = wt1;
#pragma unroll
        for (int o = 1; o < 32; o <<= 1) {
            float u0 = __shfl_up_sync(FULLM, a0, o);
            float u1 = __shfl_up_sync(FULLM, a1, o);
            float v0 = __shfl_up_sync(FULLM, b0, o);
            float v1 = __shfl_up_sync(FULLM, b1, o);
            if (lane >= o) { a0 += u0; a1 += u1; b0 += v0; b1 += v1; }
        }
        float T0  = __shfl_sync(FULLM, a0, 31);
        float TW0 = __shfl_sync(FULLM, b0, 31);
        a1 += T0; b1 += TW0;
        float e0 = a0 - w0,  e1 = a1 - w1;
        float f0 = b0 - wt0, f1 = b1 - wt1;
        float cwTot  = __shfl_sync(FULLM, a1, 31);
        float cwtTot = __shfl_sync(FULLM, b1, 31);
        float V0 = e0 * (lane * WIDTH) - f0;
        float V1 = e1 * ((lane + 32) * WIDTH) - f1;
        bool fl0 = (lane >= P0B) &&
                   (V0 + fmaxf(e0 + mWp[lane], 0.f) * WIDTH >= theta);
        bool fl1 = (V1 + fmaxf(e1 + mWp[lane + 32], 0.f) * WIDTH >= theta);
        unsigned m0 = __ballot_sync(FULLM, fl0);
        unsigned m1 = __ballot_sync(FULLM, fl1);

        while (m0) {
            int j = __ffs(m0) - 1;
            m0 &= m0 - 1;
            float cw0  = __shfl_sync(FULLM, e0, j);
            float cwt0 = __shfl_sync(FULLM, f0, j);
            if (gse(j, theta, cw0, cwt0, sp, dT, wT,
                    bufT[wid], bufW[wid], lane, &res)) { done = true; break; }
        }
        while (!done && m1) {
            int jl = __ffs(m1) - 1;
            m1 &= m1 - 1;
            float cw0  = __shfl_sync(FULLM, e1, jl);
            float cwt0 = __shfl_sync(FULLM, f1, jl);
            if (gse(jl + 32, theta, cw0, cwt0, sp, dT, wT,
                    bufT[wid], bufW[wid], lane, &res)) { done = true; break; }
        }
        if (!done)
            res = (cwTot > 0.f) ? (theta + cwtTot) / cwTot : CUDART_INF_F;
    }

    if (lane == 0) out[(size_t)b * POSTN + post] = res;
}

// ---------------------------------------------------------------------------
extern "C" void kernel_launch(void* const* d_in, const int* in_sizes, int n_in,
                              void* d_out, int out_size)
{
    const float* spikes  = (const float*)d_in[0];  // [32, 1024]
    const float* weights = (const float*)d_in[1];  // [1024, 1024]
    const float* delays  = (const float*)d_in[2];  // [1024, 1024]
    const float* thr     = (const float*)d_in[3];  // [1024]
    float* out = (float*)d_out;                    // [32, 1024]

    dim3 tb(32, 8);
    dim3 tg(POSTN / 32, PRE / 32);
    transpose_kernel<<<tg, tb>>>(weights, delays);

    equaltime_kernel<<<(BATCH * POSTN) / NWARP, NTH>>>(spikes, thr, out);
}